// round 6
// baseline (speedup 1.0000x reference)
#include <cuda_runtime.h>
#include <cstdint>

// C = triu(A @ B), A,B upper-triangular fp32, N=4096, sm_103 base target.
// Legacy tensor path: mma.sync.m16n8k8 tf32, 3-product split
//   hi = x & 0xFFFFE000, lo = tf32(x - hi);  C = Ahi*Bhi + Ahi*Blo + Alo*Bhi
//
// R4: occupancy 2 (16 warps/SM). __launch_bounds__(256,2) caps regs at 128;
// fragment loads staged (ah/bh -> pass1, bl -> pass2, al replaces ah -> pass3)
// to keep peak liveness ~120 regs. 128x128 tile, BK=16, double-buffered smem,
// conflict-free pitches (A:20, B:136). Triangular k-range per tile; longest
// tiles first; strictly-lower blocks zero-filled by tail CTAs.

#define NN 4096
#define BK 16
#define THREADS 256
#define N_WORK 528
#define N_ZERO 496

#define APITCH 20
#define BPITCH 136
#define A_SZ (128 * APITCH)
#define B_SZ (BK * BPITCH)
#define OAHI 0
#define OALO A_SZ
#define OBHI (2 * A_SZ)
#define OBLO (2 * A_SZ + B_SZ)
#define BUF_FLOATS (2 * A_SZ + 2 * B_SZ)      // 9472
#define SMEM_BYTES (2 * BUF_FLOATS * 4)       // 75776 (x2 CTAs = 151.5 KB)

static __device__ __forceinline__ float tf32hi(float x) {
    return __uint_as_float(__float_as_uint(x) & 0xFFFFE000u);
}
static __device__ __forceinline__ uint32_t tf32lo(float x, float hi) {
    float r;
    asm("cvt.rna.tf32.f32 %0, %1;" : "=f"(r) : "f"(x - hi));
    return __float_as_uint(r);
}
static __device__ __forceinline__ void mma8(float* d, const uint32_t* a,
                                            const uint32_t* b) {
    asm volatile(
        "mma.sync.aligned.m16n8k8.row.col.f32.tf32.tf32.f32 "
        "{%0,%1,%2,%3}, {%4,%5,%6,%7}, {%8,%9}, {%0,%1,%2,%3};"
        : "+f"(d[0]), "+f"(d[1]), "+f"(d[2]), "+f"(d[3])
        : "r"(a[0]), "r"(a[1]), "r"(a[2]), "r"(a[3]), "r"(b[0]), "r"(b[1]));
}
// Split one float4 into tf32 hi/lo and store both to smem.
static __device__ __forceinline__ void stage4(float* dhi, float* dlo, float4 v) {
    float4 h;
    h.x = tf32hi(v.x); h.y = tf32hi(v.y); h.z = tf32hi(v.z); h.w = tf32hi(v.w);
    uint4 l;
    l.x = tf32lo(v.x, h.x); l.y = tf32lo(v.y, h.y);
    l.z = tf32lo(v.z, h.z); l.w = tf32lo(v.w, h.w);
    *reinterpret_cast<float4*>(dhi) = h;
    *reinterpret_cast<uint4*>(dlo) = l;
}

__global__ __launch_bounds__(THREADS, 2)
void triu_mm_mma(const float* __restrict__ A, const float* __restrict__ B,
                 float* __restrict__ C) {
    const int t = blockIdx.x;
    const int tid = threadIdx.x;

    if (t >= N_WORK) {
        int rem = t - N_WORK, bi = 0, bj = 0;
        #pragma unroll 1
        for (int db = 1; db < 32; ++db) {
            int c = 32 - db;
            if (rem < c) { bj = rem; bi = rem + db; break; }
            rem -= c;
        }
        const float4 z = make_float4(0.f, 0.f, 0.f, 0.f);
        const int rowBase = bi * 128, colBase = bj * 128;
        #pragma unroll
        for (int it = 0; it < 16; ++it) {
            int idx = it * 256 + tid;
            int r = idx >> 5, c4 = idx & 31;
            *reinterpret_cast<float4*>(
                C + (size_t)(rowBase + r) * NN + colBase + c4 * 4) = z;
        }
        return;
    }

    int bi = 0, bj = 0;
    {
        int rem = t;
        #pragma unroll 1
        for (int d = 31; d >= 0; --d) {
            int c = 32 - d;
            if (rem < c) { bi = rem; bj = rem + d; break; }
            rem -= c;
        }
    }
    const int rowBase = bi * 128, colBase = bj * 128;
    const int kStart = rowBase, kEnd = colBase + 128;

    extern __shared__ float smem[];

    const int lane = tid & 31, wid = tid >> 5;
    const int wm = (wid & 1) * 64;
    const int wn = (wid >> 1) * 32;
    const int g = lane >> 2, tq = lane & 3;

    const int am0 = tid >> 2, aq0 = tid & 3;
    const int am1 = (tid + 256) >> 2, aq1 = aq0;
    const int bk0 = tid >> 5, bn40 = tid & 31;
    const int bk1 = (tid + 256) >> 5, bn41 = bn40;

    float acc[4][4][4];
    #pragma unroll
    for (int mt = 0; mt < 4; ++mt)
        #pragma unroll
        for (int nt = 0; nt < 4; ++nt)
            #pragma unroll
            for (int i = 0; i < 4; ++i) acc[mt][nt][i] = 0.f;

    float4 pa0, pa1, pb0, pb1;
    {
        const float* ab = A + (size_t)rowBase * NN + kStart;
        pa0 = *reinterpret_cast<const float4*>(ab + (size_t)am0 * NN + aq0 * 4);
        pa1 = *reinterpret_cast<const float4*>(ab + (size_t)am1 * NN + aq1 * 4);
        const float* bb = B + (size_t)kStart * NN + colBase;
        pb0 = *reinterpret_cast<const float4*>(bb + (size_t)bk0 * NN + bn40 * 4);
        pb1 = *reinterpret_cast<const float4*>(bb + (size_t)bk1 * NN + bn41 * 4);
    }

    const int nSteps = (kEnd - kStart) / BK;
    int curBuf = 0;

    {
        float* buf = smem;
        stage4(buf + OAHI + am0 * APITCH + aq0 * 4,
               buf + OALO + am0 * APITCH + aq0 * 4, pa0);
        stage4(buf + OAHI + am1 * APITCH + aq1 * 4,
               buf + OALO + am1 * APITCH + aq1 * 4, pa1);
        stage4(buf + OBHI + bk0 * BPITCH + bn40 * 4,
               buf + OBLO + bk0 * BPITCH + bn40 * 4, pb0);
        stage4(buf + OBHI + bk1 * BPITCH + bn41 * 4,
               buf + OBLO + bk1 * BPITCH + bn41 * 4, pb1);
    }
    __syncthreads();

    #pragma unroll 1
    for (int step = 0; step < nSteps; ++step) {
        const int kNext = kStart + (step + 1) * BK;
        const bool hasNext = (step + 1) < nSteps;

        if (hasNext) {
            const float* ab = A + (size_t)rowBase * NN + kNext;
            pa0 = *reinterpret_cast<const float4*>(ab + (size_t)am0 * NN + aq0 * 4);
            pa1 = *reinterpret_cast<const float4*>(ab + (size_t)am1 * NN + aq1 * 4);
            const float* bb = B + (size_t)kNext * NN + colBase;
            pb0 = *reinterpret_cast<const float4*>(bb + (size_t)bk0 * NN + bn40 * 4);
            pb1 = *reinterpret_cast<const float4*>(bb + (size_t)bk1 * NN + bn41 * 4);
        }

        const float* buf = smem + curBuf * BUF_FLOATS;
        #pragma unroll
        for (int s = 0; s < 2; ++s) {
            const int kk = s * 8 + tq;

            // Pass 1: Ahi x Bhi  (staged loads keep peak regs low)
            uint32_t ah[4][4], bh[4][2];
            #pragma unroll
            for (int mt = 0; mt < 4; ++mt) {
                const int r0 = wm + mt * 16 + g;
                ah[mt][0] = __float_as_uint(buf[OAHI + r0 * APITCH + kk]);
                ah[mt][1] = __float_as_uint(buf[OAHI + (r0 + 8) * APITCH + kk]);
                ah[mt][2] = __float_as_uint(buf[OAHI + r0 * APITCH + kk + 4]);
                ah[mt][3] = __float_as_uint(buf[OAHI + (r0 + 8) * APITCH + kk + 4]);
            }
            #pragma unroll
            for (int nt = 0; nt < 4; ++nt) {
                const int c0 = wn + nt * 8 + g;
                bh[nt][0] = __float_as_uint(buf[OBHI + kk * BPITCH + c0]);
                bh[nt][1] = __float_as_uint(buf[OBHI + (kk + 4) * BPITCH + c0]);
            }
            #pragma unroll
            for (int mt = 0; mt < 4; ++mt)
                #pragma unroll
                for (int nt = 0; nt < 4; ++nt)
                    mma8(acc[mt][nt], ah[mt], bh[nt]);

            // Pass 2: Ahi x Blo
            uint32_t bl[4][2];
            #pragma unroll
            for (int nt = 0; nt < 4; ++nt) {
                const int c0 = wn + nt * 8 + g;
                bl[nt][0] = __float_as_uint(buf[OBLO + kk * BPITCH + c0]);
                bl[nt][1] = __float_as_uint(buf[OBLO + (kk + 4) * BPITCH + c0]);
            }
            #pragma unroll
            for (int mt = 0; mt < 4; ++mt)
                #pragma unroll
                for (int nt = 0; nt < 4; ++nt)
                    mma8(acc[mt][nt], ah[mt], bl[nt]);

            // Pass 3: Alo x Bhi  (al reuses ah's registers)
            uint32_t al[4][4];
            #pragma unroll
            for (int mt = 0; mt < 4; ++mt) {
                const int r0 = wm + mt * 16 + g;
                al[mt][0] = __float_as_uint(buf[OALO + r0 * APITCH + kk]);
                al[mt][1] = __float_as_uint(buf[OALO + (r0 + 8) * APITCH + kk]);
                al[mt][2] = __float_as_uint(buf[OALO + r0 * APITCH + kk + 4]);
                al[mt][3] = __float_as_uint(buf[OALO + (r0 + 8) * APITCH + kk + 4]);
            }
            #pragma unroll
            for (int mt = 0; mt < 4; ++mt)
                #pragma unroll
                for (int nt = 0; nt < 4; ++nt)
                    mma8(acc[mt][nt], al[mt], bh[nt]);
        }

        if (hasNext) {
            float* nb = smem + (curBuf ^ 1) * BUF_FLOATS;
            stage4(nb + OAHI + am0 * APITCH + aq0 * 4,
                   nb + OALO + am0 * APITCH + aq0 * 4, pa0);
            stage4(nb + OAHI + am1 * APITCH + aq1 * 4,
                   nb + OALO + am1 * APITCH + aq1 * 4, pa1);
            stage4(nb + OBHI + bk0 * BPITCH + bn40 * 4,
                   nb + OBLO + bk0 * BPITCH + bn40 * 4, pb0);
            stage4(nb + OBHI + bk1 * BPITCH + bn41 * 4,
                   nb + OBLO + bk1 * BPITCH + bn41 * 4, pb1);
            curBuf ^= 1;
        }
        __syncthreads();
    }

    #pragma unroll
    for (int mt = 0; mt < 4; ++mt) {
        #pragma unroll
        for (int nt = 0; nt < 4; ++nt) {
            const int r0 = rowBase + wm + mt * 16 + g;
            const int c0 = colBase + wn + nt * 8 + tq * 2;
            float2 v01 = make_float2(acc[mt][nt][0], acc[mt][nt][1]);
            float2 v23 = make_float2(acc[mt][nt][2], acc[mt][nt][3]);
            *reinterpret_cast<float2*>(C + (size_t)r0 * NN + c0) = v01;
            *reinterpret_cast<float2*>(C + (size_t)(r0 + 8) * NN + c0) = v23;
        }
    }
}

extern "C" void kernel_launch(void* const* d_in, const int* in_sizes, int n_in,
                              void* d_out, int out_size) {
    const float* A = (const float*)d_in[0];
    const float* B = (const float*)d_in[1];
    float* C = (float*)d_out;

    cudaFuncSetAttribute(triu_mm_mma,
                         cudaFuncAttributeMaxDynamicSharedMemorySize, SMEM_BYTES);
    triu_mm_mma<<<N_WORK + N_ZERO, THREADS, SMEM_BYTES>>>(A, B, C);
}

// round 9
// speedup vs baseline: 1.2604x; 1.2604x over previous
#include <cuda_runtime.h>
#include <cstdint>

// C = triu(A @ B), A,B upper-triangular fp32, N=4096, sm_103 base target.
// Legacy tensor path: mma.sync.m16n8k8 tf32, 3-product split
//   hi = x & 0xFFFFE000, lo = tf32(x - hi);  C = Ahi*Bhi + Ahi*Blo + Alo*Bhi
//
// R8 (= R6 resubmit; container infra failure last round): 512-thread CTA
// (16 warps/SM structurally — no reg cap, no spills). 128x128 CTA tile,
// warp tile 32x32 (acc = 32 regs/thread), BK=16 double-buffered smem,
// conflict-free pitches (A:20, B:136). Triangular k-range per tile
// [bi*128,(bj+1)*128); longest tiles first; strictly-lower blocks
// zero-filled by tail CTAs.

#define NN 4096
#define BK 16
#define THREADS 512
#define N_WORK 528
#define N_ZERO 496

#define APITCH 20
#define BPITCH 136
#define A_SZ (128 * APITCH)
#define B_SZ (BK * BPITCH)
#define OAHI 0
#define OALO A_SZ
#define OBHI (2 * A_SZ)
#define OBLO (2 * A_SZ + B_SZ)
#define BUF_FLOATS (2 * A_SZ + 2 * B_SZ)      // 9472
#define SMEM_BYTES (2 * BUF_FLOATS * 4)       // 75776

static __device__ __forceinline__ float tf32hi(float x) {
    return __uint_as_float(__float_as_uint(x) & 0xFFFFE000u);
}
static __device__ __forceinline__ uint32_t tf32lo(float x, float hi) {
    float r;
    asm("cvt.rna.tf32.f32 %0, %1;" : "=f"(r) : "f"(x - hi));
    return __float_as_uint(r);
}
static __device__ __forceinline__ void mma8(float* d, const uint32_t* a,
                                            const uint32_t* b) {
    asm volatile(
        "mma.sync.aligned.m16n8k8.row.col.f32.tf32.tf32.f32 "
        "{%0,%1,%2,%3}, {%4,%5,%6,%7}, {%8,%9}, {%0,%1,%2,%3};"
        : "+f"(d[0]), "+f"(d[1]), "+f"(d[2]), "+f"(d[3])
        : "r"(a[0]), "r"(a[1]), "r"(a[2]), "r"(a[3]), "r"(b[0]), "r"(b[1]));
}
static __device__ __forceinline__ void stage4(float* dhi, float* dlo, float4 v) {
    float4 h;
    h.x = tf32hi(v.x); h.y = tf32hi(v.y); h.z = tf32hi(v.z); h.w = tf32hi(v.w);
    uint4 l;
    l.x = tf32lo(v.x, h.x); l.y = tf32lo(v.y, h.y);
    l.z = tf32lo(v.z, h.z); l.w = tf32lo(v.w, h.w);
    *reinterpret_cast<float4*>(dhi) = h;
    *reinterpret_cast<uint4*>(dlo) = l;
}

__global__ __launch_bounds__(THREADS, 1)
void triu_mm_mma(const float* __restrict__ A, const float* __restrict__ B,
                 float* __restrict__ C) {
    const int t = blockIdx.x;
    const int tid = threadIdx.x;

    if (t >= N_WORK) {
        // Strictly-lower 128x128 block: exactly zero.
        int rem = t - N_WORK, bi = 0, bj = 0;
        #pragma unroll 1
        for (int db = 1; db < 32; ++db) {
            int c = 32 - db;
            if (rem < c) { bj = rem; bi = rem + db; break; }
            rem -= c;
        }
        const float4 z = make_float4(0.f, 0.f, 0.f, 0.f);
        const int rowBase = bi * 128, colBase = bj * 128;
        #pragma unroll
        for (int it = 0; it < 8; ++it) {
            int idx = it * 512 + tid;
            int r = idx >> 5, c4 = idx & 31;
            *reinterpret_cast<float4*>(
                C + (size_t)(rowBase + r) * NN + colBase + c4 * 4) = z;
        }
        return;
    }

    int bi = 0, bj = 0;
    {
        int rem = t;
        #pragma unroll 1
        for (int d = 31; d >= 0; --d) {
            int c = 32 - d;
            if (rem < c) { bi = rem; bj = rem + d; break; }
            rem -= c;
        }
    }
    const int rowBase = bi * 128, colBase = bj * 128;
    const int kStart = rowBase, kEnd = colBase + 128;

    extern __shared__ float smem[];

    const int lane = tid & 31, wid = tid >> 5;
    const int wm = (wid & 3) * 32;        // warp m-offset (4 warps down)
    const int wn = (wid >> 2) * 32;       // warp n-offset (4 warps across)
    const int g = lane >> 2, tq = lane & 3;

    // Loaders: exactly one float4 per operand per thread.
    const int am = tid >> 2, aq = tid & 3;    // A: 128 rows x 4 quads
    const int bk = tid >> 5, bn4 = tid & 31;  // B: 16 k-rows x 32 quads

    float acc[2][4][4];
    #pragma unroll
    for (int mt = 0; mt < 2; ++mt)
        #pragma unroll
        for (int nt = 0; nt < 4; ++nt)
            #pragma unroll
            for (int i = 0; i < 4; ++i) acc[mt][nt][i] = 0.f;

    float4 pa, pb;
    {
        pa = *reinterpret_cast<const float4*>(
            A + (size_t)(rowBase + am) * NN + kStart + aq * 4);
        pb = *reinterpret_cast<const float4*>(
            B + (size_t)(kStart + bk) * NN + colBase + bn4 * 4);
    }

    const int nSteps = (kEnd - kStart) / BK;
    int curBuf = 0;

    stage4(smem + OAHI + am * APITCH + aq * 4,
           smem + OALO + am * APITCH + aq * 4, pa);
    stage4(smem + OBHI + bk * BPITCH + bn4 * 4,
           smem + OBLO + bk * BPITCH + bn4 * 4, pb);
    __syncthreads();

    #pragma unroll 1
    for (int step = 0; step < nSteps; ++step) {
        const int kNext = kStart + (step + 1) * BK;
        const bool hasNext = (step + 1) < nSteps;

        if (hasNext) {
            pa = *reinterpret_cast<const float4*>(
                A + (size_t)(rowBase + am) * NN + kNext + aq * 4);
            pb = *reinterpret_cast<const float4*>(
                B + (size_t)(kNext + bk) * NN + colBase + bn4 * 4);
        }

        const float* buf = smem + curBuf * BUF_FLOATS;
        #pragma unroll
        for (int s = 0; s < 2; ++s) {
            const int kk = s * 8 + tq;

            // Pass 1: Ahi x Bhi
            uint32_t ah[2][4], bh[4][2];
            #pragma unroll
            for (int mt = 0; mt < 2; ++mt) {
                const int r0 = wm + mt * 16 + g;
                ah[mt][0] = __float_as_uint(buf[OAHI + r0 * APITCH + kk]);
                ah[mt][1] = __float_as_uint(buf[OAHI + (r0 + 8) * APITCH + kk]);
                ah[mt][2] = __float_as_uint(buf[OAHI + r0 * APITCH + kk + 4]);
                ah[mt][3] = __float_as_uint(buf[OAHI + (r0 + 8) * APITCH + kk + 4]);
            }
            #pragma unroll
            for (int nt = 0; nt < 4; ++nt) {
                const int c0 = wn + nt * 8 + g;
                bh[nt][0] = __float_as_uint(buf[OBHI + kk * BPITCH + c0]);
                bh[nt][1] = __float_as_uint(buf[OBHI + (kk + 4) * BPITCH + c0]);
            }
            #pragma unroll
            for (int mt = 0; mt < 2; ++mt)
                #pragma unroll
                for (int nt = 0; nt < 4; ++nt)
                    mma8(acc[mt][nt], ah[mt], bh[nt]);

            // Pass 2: Ahi x Blo
            uint32_t bl[4][2];
            #pragma unroll
            for (int nt = 0; nt < 4; ++nt) {
                const int c0 = wn + nt * 8 + g;
                bl[nt][0] = __float_as_uint(buf[OBLO + kk * BPITCH + c0]);
                bl[nt][1] = __float_as_uint(buf[OBLO + (kk + 4) * BPITCH + c0]);
            }
            #pragma unroll
            for (int mt = 0; mt < 2; ++mt)
                #pragma unroll
                for (int nt = 0; nt < 4; ++nt)
                    mma8(acc[mt][nt], ah[mt], bl[nt]);

            // Pass 3: Alo x Bhi (al reuses ah registers)
            uint32_t al[2][4];
            #pragma unroll
            for (int mt = 0; mt < 2; ++mt) {
                const int r0 = wm + mt * 16 + g;
                al[mt][0] = __float_as_uint(buf[OALO + r0 * APITCH + kk]);
                al[mt][1] = __float_as_uint(buf[OALO + (r0 + 8) * APITCH + kk]);
                al[mt][2] = __float_as_uint(buf[OALO + r0 * APITCH + kk + 4]);
                al[mt][3] = __float_as_uint(buf[OALO + (r0 + 8) * APITCH + kk + 4]);
            }
            #pragma unroll
            for (int mt = 0; mt < 2; ++mt)
                #pragma unroll
                for (int nt = 0; nt < 4; ++nt)
                    mma8(acc[mt][nt], al[mt], bh[nt]);
        }

        if (hasNext) {
            float* nb = smem + (curBuf ^ 1) * BUF_FLOATS;
            stage4(nb + OAHI + am * APITCH + aq * 4,
                   nb + OALO + am * APITCH + aq * 4, pa);
            stage4(nb + OBHI + bk * BPITCH + bn4 * 4,
                   nb + OBLO + bk * BPITCH + bn4 * 4, pb);
            curBuf ^= 1;
        }
        __syncthreads();
    }

    #pragma unroll
    for (int mt = 0; mt < 2; ++mt) {
        #pragma unroll
        for (int nt = 0; nt < 4; ++nt) {
            const int r0 = rowBase + wm + mt * 16 + g;
            const int c0 = colBase + wn + nt * 8 + tq * 2;
            float2 v01 = make_float2(acc[mt][nt][0], acc[mt][nt][1]);
            float2 v23 = make_float2(acc[mt][nt][2], acc[mt][nt][3]);
            *reinterpret_cast<float2*>(C + (size_t)r0 * NN + c0) = v01;
            *reinterpret_cast<float2*>(C + (size_t)(r0 + 8) * NN + c0) = v23;
        }
    }
}

extern "C" void kernel_launch(void* const* d_in, const int* in_sizes, int n_in,
                              void* d_out, int out_size) {
    const float* A = (const float*)d_in[0];
    const float* B = (const float*)d_in[1];
    float* C = (float*)d_out;

    cudaFuncSetAttribute(triu_mm_mma,
                         cudaFuncAttributeMaxDynamicSharedMemorySize, SMEM_BYTES);
    triu_mm_mma<<<N_WORK + N_ZERO, THREADS, SMEM_BYTES>>>(A, B, C);
}

// round 10
// speedup vs baseline: 1.2962x; 1.0284x over previous
#include <cuda_runtime.h>
#include <cstdint>

// C = triu(A @ B), A,B upper-triangular fp32, N=4096, sm_103 base target.
// mma.sync.m16n8k8 tf32, 3-product split:
//   hi = x & 0xFFFFE000, lo = tf32(x - hi);  C = Ahi*Bhi + Ahi*Blo + Alo*Bhi
//
// R9: 128-thread CTA, 4 warps of 64x64 (acc=128 regs; LDS/mma ratio 0.67).
// Raw fp32 staged in smem via cp.async (BK=32, 3-stage pipeline, one
// __syncthreads per k-step); hi/lo split done at fragment-load time (ALU is
// idle). smem 107.5KB -> 2 CTAs/SM co-resident: 2 independent mma streams
// per SMSP cover each other's bubbles. Triangular k-range per tile; longest
// tiles first; strictly-lower blocks zero-filled by tail CTAs.

#define NN 4096
#define BK 32
#define THREADS 128
#define N_WORK 528
#define N_ZERO 496

#define APITCH 36                    // 32 + 4 pad (bank: g*4+tq all-distinct)
#define BPITCH 136                   // 128 + 8 pad (bank: tq*8+g all-distinct)
#define A_FL (128 * APITCH)          // 4608 floats
#define B_FL (BK * BPITCH)           // 4352 floats
#define BUF_FL (A_FL + B_FL)         // 8960 floats
#define NBUF 3
#define SMEM_BYTES (NBUF * BUF_FL * 4)   // 107520

static __device__ __forceinline__ float tf32hi(float x) {
    return __uint_as_float(__float_as_uint(x) & 0xFFFFE000u);
}
static __device__ __forceinline__ uint32_t tf32lo(float x, float hi) {
    float r;
    asm("cvt.rna.tf32.f32 %0, %1;" : "=f"(r) : "f"(x - hi));
    return __float_as_uint(r);
}
static __device__ __forceinline__ void mma8(float* d, const uint32_t* a,
                                            const uint32_t* b) {
    asm volatile(
        "mma.sync.aligned.m16n8k8.row.col.f32.tf32.tf32.f32 "
        "{%0,%1,%2,%3}, {%4,%5,%6,%7}, {%8,%9}, {%0,%1,%2,%3};"
        : "+f"(d[0]), "+f"(d[1]), "+f"(d[2]), "+f"(d[3])
        : "r"(a[0]), "r"(a[1]), "r"(a[2]), "r"(a[3]), "r"(b[0]), "r"(b[1]));
}
static __device__ __forceinline__ void cp16(uint32_t dst, const void* src) {
    asm volatile("cp.async.cg.shared.global [%0], [%1], 16;"
                 :: "r"(dst), "l"(src));
}
static __device__ __forceinline__ uint32_t smem_u32(const void* p) {
    uint32_t a;
    asm("{ .reg .u64 t; cvta.to.shared.u64 t, %1; cvt.u32.u64 %0, t; }"
        : "=r"(a) : "l"(p));
    return a;
}

// Issue cp.async loads of one BK=32 tile (A 128x32, B 32x128) into buffer.
static __device__ __forceinline__ void issue_tile(
    const float* __restrict__ A, const float* __restrict__ B,
    uint32_t sdst, int rowBase, int colBase, int k0, int tid) {
    // A: 1024 16B-chunks; 8 per thread. row = idx/8, quad = idx%8.
    #pragma unroll
    for (int c = 0; c < 8; ++c) {
        int idx = c * 128 + tid;
        int row = idx >> 3, q = idx & 7;
        cp16(sdst + (uint32_t)(row * APITCH + q * 4) * 4u,
             A + (size_t)(rowBase + row) * NN + k0 + q * 4);
    }
    // B: 1024 chunks; krow = idx/32, quad = idx%32.
    #pragma unroll
    for (int c = 0; c < 8; ++c) {
        int idx = c * 128 + tid;
        int kr = idx >> 5, q = idx & 31;
        cp16(sdst + (uint32_t)(A_FL + kr * BPITCH + q * 4) * 4u,
             B + (size_t)(k0 + kr) * NN + colBase + q * 4);
    }
}

__global__ __launch_bounds__(THREADS)
void triu_mm_mma(const float* __restrict__ A, const float* __restrict__ B,
                 float* __restrict__ C) {
    const int t = blockIdx.x;
    const int tid = threadIdx.x;

    if (t >= N_WORK) {
        // Strictly-lower 128x128 block: exactly zero.
        int rem = t - N_WORK, bi = 0, bj = 0;
        #pragma unroll 1
        for (int db = 1; db < 32; ++db) {
            int c = 32 - db;
            if (rem < c) { bj = rem; bi = rem + db; break; }
            rem -= c;
        }
        const float4 z = make_float4(0.f, 0.f, 0.f, 0.f);
        const int rowBase = bi * 128, colBase = bj * 128;
        #pragma unroll
        for (int it = 0; it < 32; ++it) {
            int idx = it * 128 + tid;
            int r = idx >> 5, c4 = idx & 31;
            *reinterpret_cast<float4*>(
                C + (size_t)(rowBase + r) * NN + colBase + c4 * 4) = z;
        }
        return;
    }

    int bi = 0, bj = 0;
    {
        int rem = t;
        #pragma unroll 1
        for (int d = 31; d >= 0; --d) {
            int c = 32 - d;
            if (rem < c) { bi = rem; bj = rem + d; break; }
            rem -= c;
        }
    }
    const int rowBase = bi * 128, colBase = bj * 128;
    const int kStart = rowBase, kEnd = colBase + 128;
    const int nSteps = (kEnd - kStart) / BK;   // >= 4

    extern __shared__ float smem[];
    const uint32_t sbase = smem_u32(smem);

    const int lane = tid & 31, wid = tid >> 5;
    const int wm = (wid & 1) * 64;        // warp m-offset
    const int wn = (wid >> 1) * 64;       // warp n-offset
    const int g = lane >> 2, tq = lane & 3;

    float acc[4][8][4];
    #pragma unroll
    for (int mt = 0; mt < 4; ++mt)
        #pragma unroll
        for (int nt = 0; nt < 8; ++nt)
            #pragma unroll
            for (int i = 0; i < 4; ++i) acc[mt][nt][i] = 0.f;

    // Prologue: stage 0 and 1 in flight.
    issue_tile(A, B, sbase, rowBase, colBase, kStart, tid);
    asm volatile("cp.async.commit_group;" ::: "memory");
    issue_tile(A, B, sbase + BUF_FL * 4u, rowBase, colBase, kStart + BK, tid);
    asm volatile("cp.async.commit_group;" ::: "memory");

    #pragma unroll 1
    for (int i = 0; i < nSteps; ++i) {
        asm volatile("cp.async.wait_group 1;" ::: "memory");
        __syncthreads();

        // Issue stage i+2 into buffer (i+2)%3 (free: last read at step i-1,
        // all warps past that compute as of the barrier above).
        if (i + 2 < nSteps) {
            issue_tile(A, B, sbase + (uint32_t)((i + 2) % 3) * (BUF_FL * 4u),
                       rowBase, colBase, kStart + (i + 2) * BK, tid);
        }
        asm volatile("cp.async.commit_group;" ::: "memory");

        const float* buf = smem + (i % 3) * BUF_FL;
        #pragma unroll
        for (int s = 0; s < 4; ++s) {
            const int kk = s * 8 + tq;

            // B fragments: raw -> hi/lo at load time.
            uint32_t bh[8][2], bl[8][2];
            #pragma unroll
            for (int nt = 0; nt < 8; ++nt) {
                const int c0 = wn + nt * 8 + g;
                float r0 = buf[A_FL + kk * BPITCH + c0];
                float r1 = buf[A_FL + (kk + 4) * BPITCH + c0];
                float h0 = tf32hi(r0), h1 = tf32hi(r1);
                bh[nt][0] = __float_as_uint(h0);
                bh[nt][1] = __float_as_uint(h1);
                bl[nt][0] = tf32lo(r0, h0);
                bl[nt][1] = tf32lo(r1, h1);
            }
            // Per mt: convert A fragment, run 3 passes over all nt.
            #pragma unroll
            for (int mt = 0; mt < 4; ++mt) {
                const int r0 = wm + mt * 16 + g;
                float a0 = buf[r0 * APITCH + kk];
                float a1 = buf[(r0 + 8) * APITCH + kk];
                float a2 = buf[r0 * APITCH + kk + 4];
                float a3 = buf[(r0 + 8) * APITCH + kk + 4];
                float h0 = tf32hi(a0), h1 = tf32hi(a1);
                float h2 = tf32hi(a2), h3 = tf32hi(a3);
                uint32_t ah[4] = {__float_as_uint(h0), __float_as_uint(h1),
                                  __float_as_uint(h2), __float_as_uint(h3)};
                uint32_t al[4] = {tf32lo(a0, h0), tf32lo(a1, h1),
                                  tf32lo(a2, h2), tf32lo(a3, h3)};
                #pragma unroll
                for (int nt = 0; nt < 8; ++nt)
                    mma8(acc[mt][nt], ah, bh[nt]);
                #pragma unroll
                for (int nt = 0; nt < 8; ++nt)
                    mma8(acc[mt][nt], ah, bl[nt]);
                #pragma unroll
                for (int nt = 0; nt < 8; ++nt)
                    mma8(acc[mt][nt], al, bh[nt]);
            }
        }
    }

    // Epilogue: fragment layout direct to global (float2, sector-coalesced).
    #pragma unroll
    for (int mt = 0; mt < 4; ++mt) {
        #pragma unroll
        for (int nt = 0; nt < 8; ++nt) {
            const int r0 = rowBase + wm + mt * 16 + g;
            const int c0 = colBase + wn + nt * 8 + tq * 2;
            float2 v01 = make_float2(acc[mt][nt][0], acc[mt][nt][1]);
            float2 v23 = make_float2(acc[mt][nt][2], acc[mt][nt][3]);
            *reinterpret_cast<float2*>(C + (size_t)r0 * NN + c0) = v01;
            *reinterpret_cast<float2*>(C + (size_t)(r0 + 8) * NN + c0) = v23;
        }
    }
}

extern "C" void kernel_launch(void* const* d_in, const int* in_sizes, int n_in,
                              void* d_out, int out_size) {
    const float* A = (const float*)d_in[0];
    const float* B = (const float*)d_in[1];
    float* C = (float*)d_out;

    cudaFuncSetAttribute(triu_mm_mma,
                         cudaFuncAttributeMaxDynamicSharedMemorySize, SMEM_BYTES);
    triu_mm_mma<<<N_WORK + N_ZERO, THREADS, SMEM_BYTES>>>(A, B, C);
}